// round 13
// baseline (speedup 1.0000x reference)
#include <cuda_runtime.h>
#include <math.h>

// ---------------- problem constants ----------------
#define B_  2
#define H_  64
#define W_  64
#define C_  96
#define DIN 192
#define NST 16
#define RNK 6
#define K_  4
#define L_  4096          // H_*W_
#define NC  64            // scan chunks
#define LC  64            // L_/NC
#define NR  38            // RNK + 2*NST
#define BK_ (B_*K_)
#define PF  8             // prefetch tile (scanC)

typedef unsigned long long u64;

// ---------------- scratch (device globals; no runtime alloc) ----------------
static __device__ float  g_xcpre[B_*L_*DIN];
static __device__ float  g_xconv[B_*L_*DIN];
static __device__ float  g_z    [B_*L_*DIN];
static __device__ float  g_xdbl [BK_*NR*L_];          // only C rows (22..37) used now
static __device__ float  g_csd  [BK_*NC*DIN];         // per-chunk sum(delta)
static __device__ float  g_chQ  [BK_*NC*NST*DIN];     // per-chunk affine offset
static __device__ float  g_h0   [BK_*NC*NST*DIN];     // chunk initial states
static __device__ float2 g_yev  [BK_*L_*DIN];         // (.x = local y, .y = exp(-cum d))
static __device__ float  g_y    [BK_*L_*DIN];         // scattered y
static __device__ float  g_psum [BK_*NC*DIN];
static __device__ float  g_gate [B_*DIN*K_];

// ---------------- packed f32x2 helpers ----------------
__device__ __forceinline__ u64 fpack2(float lo, float hi) {
    u64 d; asm("mov.b64 %0,{%1,%2};" : "=l"(d) : "f"(lo), "f"(hi)); return d;
}
__device__ __forceinline__ float2 funpack2(u64 a) {
    float2 r; asm("mov.b64 {%0,%1},%2;" : "=f"(r.x), "=f"(r.y) : "l"(a)); return r;
}
__device__ __forceinline__ u64 fmul2p(u64 a, u64 b) {
    u64 d; asm("mul.rn.f32x2 %0,%1,%2;" : "=l"(d) : "l"(a), "l"(b)); return d;
}
__device__ __forceinline__ u64 ffma2p(u64 a, u64 b, u64 c) {
    u64 d; asm("fma.rn.f32x2 %0,%1,%2,%3;" : "=l"(d) : "l"(a), "l"(b), "l"(c)); return d;
}
__device__ __forceinline__ float softplus_fast(float t) {
    return (t > 15.f) ? t : __logf(1.f + __expf(t));
}

// ---------------- kernel 1: in_proj GEMM  (8192x384x96), packed f32x2 -------
__global__ __launch_bounds__(256) void k_inproj(const float* __restrict__ x,
                                                const float* __restrict__ Win) {
    __shared__ __align__(16) float As[32][68];
    __shared__ __align__(16) float Bs[32][68];
    int tid = threadIdx.x;
    int m0 = blockIdx.y * 64;
    int n0 = blockIdx.x * 64;
    int tm = tid & 15, tn = tid >> 4;
    u64 acc2[2][4] = {};     // [i-pair][j]
    for (int k0 = 0; k0 < 96; k0 += 32) {
        #pragma unroll
        for (int q = 0; q < 2; q++) {
            int f = tid * 2 + q;
            int m = f >> 3, kq = f & 7;
            float4 v = *(const float4*)&x[(size_t)(m0 + m) * 96 + k0 + kq * 4];
            As[kq*4+0][m] = v.x; As[kq*4+1][m] = v.y;
            As[kq*4+2][m] = v.z; As[kq*4+3][m] = v.w;
        }
        #pragma unroll
        for (int q = 0; q < 2; q++) {
            int f = tid * 2 + q;
            int n = f >> 3, kq = f & 7;
            float4 v = *(const float4*)&Win[(size_t)(n0 + n) * 96 + k0 + kq * 4];
            Bs[kq*4+0][n] = v.x; Bs[kq*4+1][n] = v.y;
            Bs[kq*4+2][n] = v.z; Bs[kq*4+3][n] = v.w;
        }
        __syncthreads();
        #pragma unroll
        for (int kk = 0; kk < 32; kk++) {
            ulonglong2 a2 = *(const ulonglong2*)&As[kk][tm*4];
            float4 b4 = *(const float4*)&Bs[kk][tn*4];
            u64 bb0 = fpack2(b4.x, b4.x);
            u64 bb1 = fpack2(b4.y, b4.y);
            u64 bb2 = fpack2(b4.z, b4.z);
            u64 bb3 = fpack2(b4.w, b4.w);
            acc2[0][0] = ffma2p(a2.x, bb0, acc2[0][0]);
            acc2[1][0] = ffma2p(a2.y, bb0, acc2[1][0]);
            acc2[0][1] = ffma2p(a2.x, bb1, acc2[0][1]);
            acc2[1][1] = ffma2p(a2.y, bb1, acc2[1][1]);
            acc2[0][2] = ffma2p(a2.x, bb2, acc2[0][2]);
            acc2[1][2] = ffma2p(a2.y, bb2, acc2[1][2]);
            acc2[0][3] = ffma2p(a2.x, bb3, acc2[0][3]);
            acc2[1][3] = ffma2p(a2.y, bb3, acc2[1][3]);
        }
        __syncthreads();
    }
    #pragma unroll
    for (int p = 0; p < 2; p++) {
        #pragma unroll
        for (int j = 0; j < 4; j++) {
            float2 v = funpack2(acc2[p][j]);
            int n = n0 + tn * 4 + j;
            int m = m0 + tm * 4 + 2 * p;
            if (n < DIN) {
                g_xcpre[(size_t)m * DIN + n]       = v.x;
                g_xcpre[(size_t)(m+1) * DIN + n]   = v.y;
            } else {
                g_z[(size_t)m * DIN + (n - DIN)]     = v.x;
                g_z[(size_t)(m+1) * DIN + (n - DIN)] = v.y;
            }
        }
    }
}

// ---------------- kernel 2: depthwise 3x3 conv + bias + SiLU ----------------
__global__ __launch_bounds__(192) void k_conv(const float* __restrict__ cw,
                                              const float* __restrict__ cb) {
    int d = threadIdx.x;
    int b = blockIdx.z, y = blockIdx.y, xt = blockIdx.x;
    float w9[9];
    #pragma unroll
    for (int i = 0; i < 9; i++) w9[i] = cw[d * 9 + i];
    float bias = cb[d];
    const float* src = g_xcpre + (size_t)b * L_ * DIN;
    float*       dst = g_xconv + (size_t)b * L_ * DIN;
    for (int xi = 0; xi < 16; xi++) {
        int xx0 = xt * 16 + xi;
        float acc = bias;
        #pragma unroll
        for (int dy = -1; dy <= 1; dy++) {
            int yy = y + dy;
            if ((unsigned)yy >= 64u) continue;
            #pragma unroll
            for (int dx = -1; dx <= 1; dx++) {
                int xx = xx0 + dx;
                if ((unsigned)xx >= 64u) continue;
                acc = fmaf(src[(size_t)(yy * 64 + xx) * DIN + d], w9[(dy+1)*3 + dx+1], acc);
            }
        }
        float s = 1.f / (1.f + __expf(-acc));
        dst[(size_t)(y * 64 + xx0) * DIN + d] = acc * s;
    }
}

// ---------------- kernel 3: FUSED x_proj GEMM + scan phase A ----------------
// Phase 1: x_dbl for this chunk's 64 l's computed into smem sx (dts/B/C),
//          C rows (22..37) also written to g_xdbl for scanC.
// Phase 2: chunked scan (identical to previous k_scanA body).
__global__ __launch_bounds__(192, 4) void k_xscan(const float* __restrict__ xpw,
                                                  const float* __restrict__ dtw,
                                                  const float* __restrict__ dtb,
                                                  const float* __restrict__ Alogs,
                                                  const float* __restrict__ Dsv,
                                                  const int*   __restrict__ scan) {
    __shared__ __align__(16) float sx[LC][40];    // slot 0..5 dts, 8..23 B, 24..39 C
    __shared__ __align__(16) float xs_s[32][68];
    __shared__ float ws[42][33];
    __shared__ int   ssid[LC];
    int tid = threadIdx.x;
    int c  = blockIdx.x;
    int bk = blockIdx.y;
    int b = bk >> 2, k = bk & 3;
    int l0 = c * LC;
    if (tid < LC) ssid[tid] = scan[(size_t)k * L_ + l0 + tid];
    const float* xc = g_xconv + (size_t)b * L_ * DIN;
    // ---- phase 1: GEMM x_dbl[r][l] = sum_k xpw[r][k] * xconv[sid[l]][k] ----
    int rg = tid % 6;          // 6 r-groups: r = rg + 6j, j<7 -> rows 0..41
    int lg = tid / 6;          // 32 l-pairs
    float acc[7][2] = {};
    for (int k0 = 0; k0 < DIN; k0 += 32) {
        __syncthreads();
        for (int i = tid; i < 42 * 32; i += 192) {
            int r = i >> 5, cc = i & 31;
            ws[r][cc] = (r < NR) ? xpw[(size_t)(k * NR + r) * DIN + k0 + cc] : 0.f;
        }
        for (int i = tid; i < LC * 32; i += 192) {
            int l = i >> 5, kq = i & 31;
            xs_s[kq][l] = xc[(size_t)ssid[l] * DIN + k0 + kq];
        }
        __syncthreads();
        #pragma unroll
        for (int kk = 0; kk < 32; kk++) {
            float2 a2 = *(const float2*)&xs_s[kk][lg * 2];
            #pragma unroll
            for (int j = 0; j < 7; j++) {
                float wv = ws[rg + 6 * j][kk];
                acc[j][0] = fmaf(wv, a2.x, acc[j][0]);
                acc[j][1] = fmaf(wv, a2.y, acc[j][1]);
            }
        }
    }
    __syncthreads();
    {
        float* outp = g_xdbl + (size_t)bk * NR * L_;
        #pragma unroll
        for (int j = 0; j < 7; j++) {
            int r = rg + 6 * j;
            if (r < NR) {
                int slot = (r < 6) ? r : r + 2;
                sx[lg*2+0][slot] = acc[j][0];
                sx[lg*2+1][slot] = acc[j][1];
                if (r >= RNK + NST) {      // C rows needed by scanC
                    outp[(size_t)r * L_ + l0 + lg*2 + 0] = acc[j][0];
                    outp[(size_t)r * L_ + l0 + lg*2 + 1] = acc[j][1];
                }
            }
        }
    }
    __syncthreads();
    // ---- phase 2: scan (d = tid) ----
    int d  = tid;
    int kd = k * DIN + d;
    float wr[RNK];
    #pragma unroll
    for (int r = 0; r < RNK; r++) wr[r] = dtw[(size_t)kd * RNK + r];
    float tb = dtb[kd];
    float Dv = Dsv[kd];
    bool fast = true;
    #pragma unroll
    for (int n = 0; n < NST; n++) {
        float av = expf(Alogs[(size_t)kd * NST + n]);
        fast = fast && (fabsf(av - (float)(n + 1)) <= 1e-3f * (float)(n + 1));
    }
    if (fast) {
        u64 Hp[8];
        u64 z0 = fpack2(0.f, 0.f);
        #pragma unroll
        for (int j = 0; j < 8; j++) Hp[j] = z0;
        float ecum = 1.f;
        float sdv = 0.f;
        #pragma unroll 2
        for (int i = 0; i < LC; i++) {
            float xv = xc[(size_t)ssid[i] * DIN + d];
            float4 t0 = *(const float4*)&sx[i][0];
            float2 t1 = *(const float2*)&sx[i][4];
            float t = tb;
            t = fmaf(wr[0], t0.x, t); t = fmaf(wr[1], t0.y, t);
            t = fmaf(wr[2], t0.z, t); t = fmaf(wr[3], t0.w, t);
            t = fmaf(wr[4], t1.x, t); t = fmaf(wr[5], t1.y, t);
            float delta = softplus_fast(t);
            sdv += delta;
            float du = delta * xv;
            float e = __expf(-delta);
            ecum *= e;
            float e2f = e * e, e4f = e2f * e2f, e8f = e4f * e4f;
            u64 p0  = fpack2(e, e2f);
            u64 ee2 = fpack2(e2f, e2f);
            u64 ee4 = fpack2(e4f, e4f);
            u64 ee8 = fpack2(e8f, e8f);
            u64 p1 = fmul2p(p0, ee2);
            u64 p2 = fmul2p(p0, ee4);
            u64 p3 = fmul2p(p1, ee4);
            u64 p4 = fmul2p(p0, ee8);
            u64 p5 = fmul2p(p1, ee8);
            u64 p6 = fmul2p(p2, ee8);
            u64 p7 = fmul2p(p3, ee8);
            u64 dud = fpack2(du, du);
            const ulonglong2* Bq = (const ulonglong2*)&sx[i][8];
            const ulonglong2* Cq = (const ulonglong2*)&sx[i][24];
            ulonglong2 b01 = Bq[0], b23 = Bq[1], b45 = Bq[2], b67 = Bq[3];
            ulonglong2 c01 = Cq[0], c23 = Cq[1], c45 = Cq[2], c67 = Cq[3];
            Hp[0] = ffma2p(p0, Hp[0], fmul2p(dud, b01.x));
            Hp[1] = ffma2p(p1, Hp[1], fmul2p(dud, b01.y));
            Hp[2] = ffma2p(p2, Hp[2], fmul2p(dud, b23.x));
            Hp[3] = ffma2p(p3, Hp[3], fmul2p(dud, b23.y));
            Hp[4] = ffma2p(p4, Hp[4], fmul2p(dud, b45.x));
            Hp[5] = ffma2p(p5, Hp[5], fmul2p(dud, b45.y));
            Hp[6] = ffma2p(p6, Hp[6], fmul2p(dud, b67.x));
            Hp[7] = ffma2p(p7, Hp[7], fmul2p(dud, b67.y));
            u64 ysp = fpack2(Dv * xv, 0.f);
            ysp = ffma2p(Hp[0], c01.x, ysp);
            ysp = ffma2p(Hp[1], c01.y, ysp);
            ysp = ffma2p(Hp[2], c23.x, ysp);
            ysp = ffma2p(Hp[3], c23.y, ysp);
            ysp = ffma2p(Hp[4], c45.x, ysp);
            ysp = ffma2p(Hp[5], c45.y, ysp);
            ysp = ffma2p(Hp[6], c67.x, ysp);
            ysp = ffma2p(Hp[7], c67.y, ysp);
            float2 ys2 = funpack2(ysp);
            float ys = ys2.x + ys2.y;
            size_t gi = ((size_t)bk * L_ + l0 + i) * DIN + d;
            g_yev[gi] = make_float2(ys, ecum);
        }
        size_t basep = ((size_t)(bk * NC + c) * NST) * DIN + d;
        #pragma unroll
        for (int j = 0; j < 8; j++) {
            float2 hv = funpack2(Hp[j]);
            g_chQ[basep + (size_t)(2*j)   * DIN] = hv.x;
            g_chQ[basep + (size_t)(2*j+1) * DIN] = hv.y;
        }
        g_csd[((size_t)bk * NC + c) * DIN + d] = sdv;
    } else {
        float h[NST];
        #pragma unroll
        for (int n = 0; n < NST; n++) h[n] = 0.f;
        float a[NST];
        #pragma unroll
        for (int n = 0; n < NST; n++) a[n] = -expf(Alogs[(size_t)kd * NST + n]);
        float sdv = 0.f;
        #pragma unroll 1
        for (int i = 0; i < LC; i++) {
            float xv = xc[(size_t)ssid[i] * DIN + d];
            float4 t0 = *(const float4*)&sx[i][0];
            float2 t1 = *(const float2*)&sx[i][4];
            float t = tb;
            t = fmaf(wr[0], t0.x, t); t = fmaf(wr[1], t0.y, t);
            t = fmaf(wr[2], t0.z, t); t = fmaf(wr[3], t0.w, t);
            t = fmaf(wr[4], t1.x, t); t = fmaf(wr[5], t1.y, t);
            float delta = softplus_fast(t);
            sdv += delta;
            float du = delta * xv;
            float ys = Dv * xv;
            #pragma unroll
            for (int n = 0; n < NST; n++) {
                float dA = __expf(delta * a[n]);
                h[n] = fmaf(dA, h[n], du * sx[i][8 + n]);
                ys = fmaf(h[n], sx[i][24 + n], ys);
            }
            size_t gi = ((size_t)bk * L_ + l0 + i) * DIN + d;
            g_yev[gi] = make_float2(ys, sdv);
        }
        size_t basep = ((size_t)(bk * NC + c) * NST) * DIN + d;
        #pragma unroll
        for (int n = 0; n < NST; n++)
            g_chQ[basep + (size_t)n * DIN] = h[n];
        g_csd[((size_t)bk * NC + c) * DIN + d] = sdv;
    }
}

// ---------------- kernel 5: scan phase B (serial chunk chain) ----------------
__global__ __launch_bounds__(192) void k_scanB(const float* __restrict__ Alogs) {
    int n  = blockIdx.x;     // state index
    int bk = blockIdx.y;
    int d  = threadIdx.x;
    int kd = (bk & 3) * DIN + d;
    float a = -expf(Alogs[(size_t)kd * NST + n]);
    float h = 0.f;
    for (int c = 0; c < NC; c++) {
        size_t base = ((size_t)(bk * NC + c) * NST + n) * DIN + d;
        g_h0[base] = h;
        float sd = g_csd[((size_t)bk * NC + c) * DIN + d];
        h = fmaf(__expf(a * sd), h, g_chQ[base]);
    }
}

// ---------------- kernel 6: scan phase C (packed Horner + ye prefetch) -------
__global__ __launch_bounds__(192, 4) void k_scanC(const float* __restrict__ Alogs,
                                                  const int*   __restrict__ scan) {
    __shared__ __align__(16) float sC[LC][20];
    __shared__ int   ssid[LC];
    int d  = threadIdx.x;
    int c  = blockIdx.x;
    int bk = blockIdx.y;
    int k = bk & 3;
    int l0 = c * LC;
    const float* xd = g_xdbl + (size_t)bk * NR * L_;
    for (int i = d; i < NST * LC; i += 192) {
        int n = i >> 6, q = i & 63;
        sC[q][n] = xd[(size_t)(RNK + NST + n) * L_ + l0 + q];
    }
    if (d < LC) ssid[d] = scan[(size_t)k * L_ + l0 + d];
    int kd = k * DIN + d;
    bool fast = true;
    #pragma unroll
    for (int n = 0; n < NST; n++) {
        float av = expf(Alogs[(size_t)kd * NST + n]);
        fast = fast && (fabsf(av - (float)(n + 1)) <= 1e-3f * (float)(n + 1));
    }
    float h0[NST]; bool any = false;
    size_t base = ((size_t)(bk * NC + c) * NST) * DIN + d;
    #pragma unroll
    for (int n = 0; n < NST; n++) {
        h0[n] = g_h0[base + (size_t)n * DIN];
        any = any || (h0[n] != 0.f);
    }
    __syncthreads();
    float* yp = g_y + (size_t)bk * L_ * DIN;
    const float2* yev = g_yev + ((size_t)bk * L_ + l0) * DIN + d;
    float sacc = 0.f;
    if (!any) {
        #pragma unroll 4
        for (int i = 0; i < LC; i++) {
            float yv = yev[(size_t)i * DIN].x;
            yp[(size_t)ssid[i] * DIN + d] = yv;
            sacc += yv;
        }
    } else if (fast) {
        u64 H0p[8];
        #pragma unroll
        for (int j = 0; j < 8; j++) H0p[j] = fpack2(h0[2*j], h0[2*j+1]);
        float2 ye[PF], yen[PF];
        #pragma unroll
        for (int j = 0; j < PF; j++) ye[j] = yev[(size_t)j * DIN];
        for (int i0 = 0; i0 < LC; i0 += PF) {
            if (i0 + PF < LC) {
                #pragma unroll
                for (int j = 0; j < PF; j++) yen[j] = yev[(size_t)(i0 + PF + j) * DIN];
            }
            #pragma unroll
            for (int j = 0; j < PF; j++) {
                int i = i0 + j;
                float yv = ye[j].x;
                float e  = ye[j].y;
                float e2f = e * e;
                u64 ee2 = fpack2(e2f, e2f);
                const ulonglong2* Cq = (const ulonglong2*)&sC[i][0];
                ulonglong2 c01 = Cq[0], c23 = Cq[1], c45 = Cq[2], c67 = Cq[3];
                u64 acc = fmul2p(c67.y, H0p[7]);
                acc = ffma2p(acc, ee2, fmul2p(c67.x, H0p[6]));
                acc = ffma2p(acc, ee2, fmul2p(c45.y, H0p[5]));
                acc = ffma2p(acc, ee2, fmul2p(c45.x, H0p[4]));
                acc = ffma2p(acc, ee2, fmul2p(c23.y, H0p[3]));
                acc = ffma2p(acc, ee2, fmul2p(c23.x, H0p[2]));
                acc = ffma2p(acc, ee2, fmul2p(c01.y, H0p[1]));
                acc = ffma2p(acc, ee2, fmul2p(c01.x, H0p[0]));
                float2 av = funpack2(acc);
                yv = fmaf(av.x, e, yv);
                yv = fmaf(av.y, e2f, yv);
                yp[(size_t)ssid[i] * DIN + d] = yv;
                sacc += yv;
            }
            #pragma unroll
            for (int j = 0; j < PF; j++) ye[j] = yen[j];
        }
    } else {
        float a[NST];
        #pragma unroll
        for (int n = 0; n < NST; n++) a[n] = -expf(Alogs[(size_t)kd * NST + n]);
        #pragma unroll 1
        for (int i = 0; i < LC; i++) {
            float2 yv2 = yev[(size_t)i * DIN];
            float yv = yv2.x;
            float sdv = yv2.y;
            float corr = 0.f;
            #pragma unroll
            for (int n = 0; n < NST; n++)
                corr = fmaf(sC[i][n] * h0[n], __expf(a[n] * sdv), corr);
            yv += corr;
            yp[(size_t)ssid[i] * DIN + d] = yv;
            sacc += yv;
        }
    }
    g_psum[((size_t)bk * NC + c) * DIN + d] = sacc;
}

// ---------------- kernel 7: gates ----------------
__global__ __launch_bounds__(192) void k_gate(const float* __restrict__ gw,
                                              const float* __restrict__ gb) {
    int b = blockIdx.x, d = threadIdx.x;
    float pooled[K_];
    #pragma unroll
    for (int k = 0; k < K_; k++) {
        float s = 0.f;
        for (int c = 0; c < NC; c++)
            s += g_psum[((size_t)(b * K_ + k) * NC + c) * DIN + d];
        pooled[k] = s * (1.f / (float)L_);
    }
    #pragma unroll
    for (int o = 0; o < K_; o++) {
        float acc = gb[d * K_ + o];
        #pragma unroll
        for (int i = 0; i < K_; i++)
            acc = fmaf(pooled[i], gw[(size_t)(d * K_ + o) * K_ + i], acc);
        g_gate[(size_t)(b * DIN + d) * K_ + o] = 1.f / (1.f + __expf(-acc));
    }
}

// ---------------- kernel 8: gate-combine + LayerNorm + SiLU(z) + out GEMM ----
__global__ __launch_bounds__(256) void k_final(const float* __restrict__ lng,
                                               const float* __restrict__ lnb,
                                               const float* __restrict__ Wout,
                                               float* __restrict__ out) {
    __shared__ float a_s[32][193];
    __shared__ float w_s[96][33];
    int tid = threadIdx.x;
    int b  = blockIdx.y;
    int l0 = blockIdx.x * 32;
    int lt = tid >> 3, st = tid & 7;
    int l = l0 + lt;
    float s1 = 0.f, s2 = 0.f;
    #pragma unroll
    for (int q = 0; q < 24; q++) {
        int d = st + 8 * q;
        float4 gt = *(const float4*)&g_gate[(size_t)(b * DIN + d) * K_];
        float v = 0.f;
        v = fmaf(gt.x, g_y[((size_t)(b * K_ + 0) * L_ + l) * DIN + d], v);
        v = fmaf(gt.y, g_y[((size_t)(b * K_ + 1) * L_ + l) * DIN + d], v);
        v = fmaf(gt.z, g_y[((size_t)(b * K_ + 2) * L_ + l) * DIN + d], v);
        v = fmaf(gt.w, g_y[((size_t)(b * K_ + 3) * L_ + l) * DIN + d], v);
        a_s[lt][d] = v;
        s1 += v; s2 = fmaf(v, v, s2);
    }
    #pragma unroll
    for (int off = 4; off >= 1; off >>= 1) {
        s1 += __shfl_xor_sync(0xffffffffu, s1, off, 8);
        s2 += __shfl_xor_sync(0xffffffffu, s2, off, 8);
    }
    float mu   = s1 * (1.f / (float)DIN);
    float var  = s2 * (1.f / (float)DIN) - mu * mu;
    float rstd = rsqrtf(var + 1e-5f);
    {
        const float* zrow = g_z + ((size_t)b * L_ + l) * DIN;
        #pragma unroll
        for (int q = 0; q < 24; q++) {
            int d = st + 8 * q;
            float v = a_s[lt][d];
            v = (v - mu) * rstd * lng[d] + lnb[d];
            float z = zrow[d];
            v *= z / (1.f + __expf(-z));
            a_s[lt][d] = v;
        }
    }
    int cg = tid & 31, lg2 = tid >> 5;
    float acc[4][3] = {};
    for (int k0 = 0; k0 < DIN; k0 += 32) {
        __syncthreads();
        for (int i = tid; i < 96 * 32; i += 256) {
            int cc = i >> 5, dd = i & 31;
            w_s[cc][dd] = Wout[(size_t)cc * DIN + k0 + dd];
        }
        __syncthreads();
        #pragma unroll 4
        for (int dd = 0; dd < 32; dd++) {
            float av[4];
            #pragma unroll
            for (int ii = 0; ii < 4; ii++) av[ii] = a_s[lg2 * 4 + ii][k0 + dd];
            #pragma unroll
            for (int jj = 0; jj < 3; jj++) {
                float wv = w_s[cg * 3 + jj][dd];
                #pragma unroll
                for (int ii = 0; ii < 4; ii++) acc[ii][jj] = fmaf(av[ii], wv, acc[ii][jj]);
            }
        }
    }
    #pragma unroll
    for (int ii = 0; ii < 4; ii++) {
        int ll = l0 + lg2 * 4 + ii;
        #pragma unroll
        for (int jj = 0; jj < 3; jj++)
            out[((size_t)b * L_ + ll) * C_ + cg * 3 + jj] = acc[ii][jj];
    }
}

// ---------------- launcher ----------------
extern "C" void kernel_launch(void* const* d_in, const int* in_sizes, int n_in,
                              void* d_out, int out_size) {
    const float* x     = (const float*)d_in[0];
    const float* Win   = (const float*)d_in[1];
    const float* convw = (const float*)d_in[2];
    const float* convb = (const float*)d_in[3];
    const float* xpw   = (const float*)d_in[4];
    const float* dtw   = (const float*)d_in[5];
    const float* dtb   = (const float*)d_in[6];
    const float* Alogs = (const float*)d_in[7];
    const float* Dsv   = (const float*)d_in[8];
    const float* gw    = (const float*)d_in[9];
    const float* gb    = (const float*)d_in[10];
    const float* lng   = (const float*)d_in[11];
    const float* lnb   = (const float*)d_in[12];
    const float* Wout  = (const float*)d_in[13];
    const int*   scan  = (const int*)d_in[14];
    float* out = (float*)d_out;

    k_inproj<<<dim3(6, 128), 256>>>(x, Win);
    k_conv  <<<dim3(4, H_, B_), 192>>>(convw, convb);
    k_xscan <<<dim3(NC, BK_), 192>>>(xpw, dtw, dtb, Alogs, Dsv, scan);
    k_scanB <<<dim3(NST, BK_), 192>>>(Alogs);
    k_scanC <<<dim3(NC, BK_), 192>>>(Alogs, scan);
    k_gate  <<<B_, 192>>>(gw, gb);
    k_final <<<dim3(L_ / 32, B_), 256>>>(lng, lnb, Wout, out);
}

// round 14
// speedup vs baseline: 1.1261x; 1.1261x over previous
#include <cuda_runtime.h>
#include <math.h>

// ---------------- problem constants ----------------
#define B_  2
#define H_  64
#define W_  64
#define C_  96
#define DIN 192
#define NST 16
#define RNK 6
#define K_  4
#define L_  4096          // H_*W_
#define NC  64            // scan chunks
#define LC  64            // L_/NC
#define NR  38            // RNK + 2*NST
#define BK_ (B_*K_)
#define PF  8             // prefetch tile

typedef unsigned long long u64;

// ---------------- scratch (device globals; no runtime alloc) ----------------
static __device__ float  g_xcpre[B_*L_*DIN];
static __device__ float  g_xconv[B_*L_*DIN];
static __device__ float  g_z    [B_*L_*DIN];
static __device__ float  g_xdbl [BK_*NR*L_];          // ((bk)*38+r)*L + l
static __device__ float  g_csd  [BK_*NC*DIN];         // per-chunk sum(delta)
static __device__ float  g_chQ  [BK_*NC*NST*DIN];     // per-chunk affine offset
static __device__ float  g_h0   [BK_*NC*NST*DIN];     // chunk initial states
static __device__ float2 g_yev  [BK_*L_*DIN];         // (.x = local y, .y = exp(-cum d))
static __device__ float  g_y    [BK_*L_*DIN];         // scattered y
static __device__ float  g_psum [BK_*NC*DIN];
static __device__ float  g_gate [B_*DIN*K_];

// ---------------- packed f32x2 helpers ----------------
__device__ __forceinline__ u64 fpack2(float lo, float hi) {
    u64 d; asm("mov.b64 %0,{%1,%2};" : "=l"(d) : "f"(lo), "f"(hi)); return d;
}
__device__ __forceinline__ float2 funpack2(u64 a) {
    float2 r; asm("mov.b64 {%0,%1},%2;" : "=f"(r.x), "=f"(r.y) : "l"(a)); return r;
}
__device__ __forceinline__ u64 fmul2p(u64 a, u64 b) {
    u64 d; asm("mul.rn.f32x2 %0,%1,%2;" : "=l"(d) : "l"(a), "l"(b)); return d;
}
__device__ __forceinline__ u64 ffma2p(u64 a, u64 b, u64 c) {
    u64 d; asm("fma.rn.f32x2 %0,%1,%2,%3;" : "=l"(d) : "l"(a), "l"(b), "l"(c)); return d;
}
__device__ __forceinline__ float softplus_fast(float t) {
    return (t > 15.f) ? t : __logf(1.f + __expf(t));
}

// ---------------- kernel 1: in_proj GEMM  (8192x384x96), packed f32x2 -------
__global__ __launch_bounds__(256) void k_inproj(const float* __restrict__ x,
                                                const float* __restrict__ Win) {
    __shared__ __align__(16) float As[32][68];
    __shared__ __align__(16) float Bs[32][68];
    int tid = threadIdx.x;
    int m0 = blockIdx.y * 64;
    int n0 = blockIdx.x * 64;
    int tm = tid & 15, tn = tid >> 4;
    u64 acc2[2][4] = {};     // [i-pair][j]
    for (int k0 = 0; k0 < 96; k0 += 32) {
        #pragma unroll
        for (int q = 0; q < 2; q++) {
            int f = tid * 2 + q;
            int m = f >> 3, kq = f & 7;
            float4 v = *(const float4*)&x[(size_t)(m0 + m) * 96 + k0 + kq * 4];
            As[kq*4+0][m] = v.x; As[kq*4+1][m] = v.y;
            As[kq*4+2][m] = v.z; As[kq*4+3][m] = v.w;
        }
        #pragma unroll
        for (int q = 0; q < 2; q++) {
            int f = tid * 2 + q;
            int n = f >> 3, kq = f & 7;
            float4 v = *(const float4*)&Win[(size_t)(n0 + n) * 96 + k0 + kq * 4];
            Bs[kq*4+0][n] = v.x; Bs[kq*4+1][n] = v.y;
            Bs[kq*4+2][n] = v.z; Bs[kq*4+3][n] = v.w;
        }
        __syncthreads();
        #pragma unroll
        for (int kk = 0; kk < 32; kk++) {
            ulonglong2 a2 = *(const ulonglong2*)&As[kk][tm*4];
            float4 b4 = *(const float4*)&Bs[kk][tn*4];
            u64 bb0 = fpack2(b4.x, b4.x);
            u64 bb1 = fpack2(b4.y, b4.y);
            u64 bb2 = fpack2(b4.z, b4.z);
            u64 bb3 = fpack2(b4.w, b4.w);
            acc2[0][0] = ffma2p(a2.x, bb0, acc2[0][0]);
            acc2[1][0] = ffma2p(a2.y, bb0, acc2[1][0]);
            acc2[0][1] = ffma2p(a2.x, bb1, acc2[0][1]);
            acc2[1][1] = ffma2p(a2.y, bb1, acc2[1][1]);
            acc2[0][2] = ffma2p(a2.x, bb2, acc2[0][2]);
            acc2[1][2] = ffma2p(a2.y, bb2, acc2[1][2]);
            acc2[0][3] = ffma2p(a2.x, bb3, acc2[0][3]);
            acc2[1][3] = ffma2p(a2.y, bb3, acc2[1][3]);
        }
        __syncthreads();
    }
    #pragma unroll
    for (int p = 0; p < 2; p++) {
        #pragma unroll
        for (int j = 0; j < 4; j++) {
            float2 v = funpack2(acc2[p][j]);
            int n = n0 + tn * 4 + j;
            int m = m0 + tm * 4 + 2 * p;
            if (n < DIN) {
                g_xcpre[(size_t)m * DIN + n]       = v.x;
                g_xcpre[(size_t)(m+1) * DIN + n]   = v.y;
            } else {
                g_z[(size_t)m * DIN + (n - DIN)]     = v.x;
                g_z[(size_t)(m+1) * DIN + (n - DIN)] = v.y;
            }
        }
    }
}

// ---------------- kernel 2: depthwise 3x3 conv + bias + SiLU ----------------
__global__ __launch_bounds__(192) void k_conv(const float* __restrict__ cw,
                                              const float* __restrict__ cb) {
    int d = threadIdx.x;
    int b = blockIdx.z, y = blockIdx.y, xt = blockIdx.x;
    float w9[9];
    #pragma unroll
    for (int i = 0; i < 9; i++) w9[i] = cw[d * 9 + i];
    float bias = cb[d];
    const float* src = g_xcpre + (size_t)b * L_ * DIN;
    float*       dst = g_xconv + (size_t)b * L_ * DIN;
    for (int xi = 0; xi < 16; xi++) {
        int xx0 = xt * 16 + xi;
        float acc = bias;
        #pragma unroll
        for (int dy = -1; dy <= 1; dy++) {
            int yy = y + dy;
            if ((unsigned)yy >= 64u) continue;
            #pragma unroll
            for (int dx = -1; dx <= 1; dx++) {
                int xx = xx0 + dx;
                if ((unsigned)xx >= 64u) continue;
                acc = fmaf(src[(size_t)(yy * 64 + xx) * DIN + d], w9[(dy+1)*3 + dx+1], acc);
            }
        }
        float s = 1.f / (1.f + __expf(-acc));
        dst[(size_t)(y * 64 + xx0) * DIN + d] = acc * s;
    }
}

// ---------------- kernel 3: x_proj GEMM with gather, packed f32x2 ------------
__global__ __launch_bounds__(128) void k_xproj(const float* __restrict__ xpw,
                                               const int*   __restrict__ scan) {
    __shared__ __align__(16) float xs_s[32][68];
    __shared__ float ws  [40][33];
    __shared__ int   sid [64];
    int tid = threadIdx.x;
    int l0  = blockIdx.x * 64;
    int bk  = blockIdx.y;
    int b = bk >> 2, k = bk & 3;
    if (tid < 64) sid[tid] = scan[(size_t)k * L_ + l0 + tid];
    int lg = tid >> 3, rg = tid & 7;
    u64 acc2[5][2] = {};       // [j][l-pair]
    const float* xc = g_xconv + (size_t)b * L_ * DIN;
    for (int k0 = 0; k0 < DIN; k0 += 32) {
        __syncthreads();
        for (int i = tid; i < NR * 32; i += 128) {
            int r = i >> 5, c = i & 31;
            ws[r][c] = xpw[(size_t)(k * NR + r) * DIN + k0 + c];
        }
        if (tid < 64) ws[38 + (tid >> 5)][tid & 31] = 0.f;
        {
            int l = tid >> 1, half = (tid & 1) * 16;
            const float* p = &xc[(size_t)sid[l] * DIN + k0 + half];
            #pragma unroll
            for (int q = 0; q < 16; q += 4) {
                float4 v = *(const float4*)(p + q);
                xs_s[half+q+0][l] = v.x; xs_s[half+q+1][l] = v.y;
                xs_s[half+q+2][l] = v.z; xs_s[half+q+3][l] = v.w;
            }
        }
        __syncthreads();
        #pragma unroll
        for (int kk = 0; kk < 32; kk++) {
            ulonglong2 a2 = *(const ulonglong2*)&xs_s[kk][lg * 4];
            #pragma unroll
            for (int j = 0; j < 5; j++) {
                float wv = ws[rg + 8 * j][kk];
                u64 ww = fpack2(wv, wv);
                acc2[j][0] = ffma2p(ww, a2.x, acc2[j][0]);
                acc2[j][1] = ffma2p(ww, a2.y, acc2[j][1]);
            }
        }
    }
    float* outp = g_xdbl + (size_t)bk * NR * L_;
    #pragma unroll
    for (int j = 0; j < 5; j++) {
        int r = rg + 8 * j;
        if (r < NR) {
            float2 v0 = funpack2(acc2[j][0]);
            float2 v1 = funpack2(acc2[j][1]);
            float* o = &outp[(size_t)r * L_ + l0 + lg * 4];
            o[0] = v0.x; o[1] = v0.y; o[2] = v1.x; o[3] = v1.y;
        }
    }
}

// ---------------- kernel 4: scan phase A (packed f32x2 states) --------------
__global__ __launch_bounds__(192, 4) void k_scanA(const float* __restrict__ dtw,
                                                  const float* __restrict__ dtb,
                                                  const float* __restrict__ Alogs,
                                                  const float* __restrict__ Dsv,
                                                  const int*   __restrict__ scan) {
    __shared__ __align__(16) float sx[LC][40];
    __shared__ int   ssid[LC];
    int d  = threadIdx.x;
    int c  = blockIdx.x;
    int bk = blockIdx.y;
    int b = bk >> 2, k = bk & 3;
    int l0 = c * LC;
    const float* xd = g_xdbl + (size_t)bk * NR * L_;
    for (int i = d; i < NR * LC; i += 192) {
        int r = i >> 6, q = i & 63;
        sx[q][r < 6 ? r : r + 2] = xd[(size_t)r * L_ + l0 + q];
    }
    if (d < LC) ssid[d] = scan[(size_t)k * L_ + l0 + d];
    int kd = k * DIN + d;
    float wr[RNK];
    #pragma unroll
    for (int r = 0; r < RNK; r++) wr[r] = dtw[(size_t)kd * RNK + r];
    float tb = dtb[kd];
    float Dv = Dsv[kd];
    bool fast = true;
    #pragma unroll
    for (int n = 0; n < NST; n++) {
        float av = expf(Alogs[(size_t)kd * NST + n]);
        fast = fast && (fabsf(av - (float)(n + 1)) <= 1e-3f * (float)(n + 1));
    }
    __syncthreads();
    const float* xc = g_xconv + (size_t)b * L_ * DIN;
    if (fast) {
        u64 Hp[8];
        u64 z0 = fpack2(0.f, 0.f);
        #pragma unroll
        for (int j = 0; j < 8; j++) Hp[j] = z0;
        float ecum = 1.f;
        float sdv = 0.f;
        #pragma unroll 2
        for (int i = 0; i < LC; i++) {
            float xv = xc[(size_t)ssid[i] * DIN + d];
            float4 t0 = *(const float4*)&sx[i][0];
            float2 t1 = *(const float2*)&sx[i][4];
            float t = tb;
            t = fmaf(wr[0], t0.x, t); t = fmaf(wr[1], t0.y, t);
            t = fmaf(wr[2], t0.z, t); t = fmaf(wr[3], t0.w, t);
            t = fmaf(wr[4], t1.x, t); t = fmaf(wr[5], t1.y, t);
            float delta = softplus_fast(t);
            sdv += delta;
            float du = delta * xv;
            float e = __expf(-delta);
            ecum *= e;
            float e2f = e * e, e4f = e2f * e2f, e8f = e4f * e4f;
            u64 p0  = fpack2(e, e2f);
            u64 ee2 = fpack2(e2f, e2f);
            u64 ee4 = fpack2(e4f, e4f);
            u64 ee8 = fpack2(e8f, e8f);
            u64 p1 = fmul2p(p0, ee2);
            u64 p2 = fmul2p(p0, ee4);
            u64 p3 = fmul2p(p1, ee4);
            u64 p4 = fmul2p(p0, ee8);
            u64 p5 = fmul2p(p1, ee8);
            u64 p6 = fmul2p(p2, ee8);
            u64 p7 = fmul2p(p3, ee8);
            u64 dud = fpack2(du, du);
            const ulonglong2* Bq = (const ulonglong2*)&sx[i][8];
            const ulonglong2* Cq = (const ulonglong2*)&sx[i][24];
            ulonglong2 b01 = Bq[0], b23 = Bq[1], b45 = Bq[2], b67 = Bq[3];
            ulonglong2 c01 = Cq[0], c23 = Cq[1], c45 = Cq[2], c67 = Cq[3];
            Hp[0] = ffma2p(p0, Hp[0], fmul2p(dud, b01.x));
            Hp[1] = ffma2p(p1, Hp[1], fmul2p(dud, b01.y));
            Hp[2] = ffma2p(p2, Hp[2], fmul2p(dud, b23.x));
            Hp[3] = ffma2p(p3, Hp[3], fmul2p(dud, b23.y));
            Hp[4] = ffma2p(p4, Hp[4], fmul2p(dud, b45.x));
            Hp[5] = ffma2p(p5, Hp[5], fmul2p(dud, b45.y));
            Hp[6] = ffma2p(p6, Hp[6], fmul2p(dud, b67.x));
            Hp[7] = ffma2p(p7, Hp[7], fmul2p(dud, b67.y));
            u64 ysp = fpack2(Dv * xv, 0.f);
            ysp = ffma2p(Hp[0], c01.x, ysp);
            ysp = ffma2p(Hp[1], c01.y, ysp);
            ysp = ffma2p(Hp[2], c23.x, ysp);
            ysp = ffma2p(Hp[3], c23.y, ysp);
            ysp = ffma2p(Hp[4], c45.x, ysp);
            ysp = ffma2p(Hp[5], c45.y, ysp);
            ysp = ffma2p(Hp[6], c67.x, ysp);
            ysp = ffma2p(Hp[7], c67.y, ysp);
            float2 ys2 = funpack2(ysp);
            float ys = ys2.x + ys2.y;
            size_t gi = ((size_t)bk * L_ + l0 + i) * DIN + d;
            g_yev[gi] = make_float2(ys, ecum);
        }
        size_t basep = ((size_t)(bk * NC + c) * NST) * DIN + d;
        #pragma unroll
        for (int j = 0; j < 8; j++) {
            float2 hv = funpack2(Hp[j]);
            g_chQ[basep + (size_t)(2*j)   * DIN] = hv.x;
            g_chQ[basep + (size_t)(2*j+1) * DIN] = hv.y;
        }
        g_csd[((size_t)bk * NC + c) * DIN + d] = sdv;
    } else {
        float h[NST];
        #pragma unroll
        for (int n = 0; n < NST; n++) h[n] = 0.f;
        float a[NST];
        #pragma unroll
        for (int n = 0; n < NST; n++) a[n] = -expf(Alogs[(size_t)kd * NST + n]);
        float sdv = 0.f;
        #pragma unroll 1
        for (int i = 0; i < LC; i++) {
            float xv = xc[(size_t)ssid[i] * DIN + d];
            float4 t0 = *(const float4*)&sx[i][0];
            float2 t1 = *(const float2*)&sx[i][4];
            float t = tb;
            t = fmaf(wr[0], t0.x, t); t = fmaf(wr[1], t0.y, t);
            t = fmaf(wr[2], t0.z, t); t = fmaf(wr[3], t0.w, t);
            t = fmaf(wr[4], t1.x, t); t = fmaf(wr[5], t1.y, t);
            float delta = softplus_fast(t);
            sdv += delta;
            float du = delta * xv;
            float ys = Dv * xv;
            #pragma unroll
            for (int n = 0; n < NST; n++) {
                float dA = __expf(delta * a[n]);
                h[n] = fmaf(dA, h[n], du * sx[i][8 + n]);
                ys = fmaf(h[n], sx[i][24 + n], ys);
            }
            size_t gi = ((size_t)bk * L_ + l0 + i) * DIN + d;
            g_yev[gi] = make_float2(ys, sdv);
        }
        size_t basep = ((size_t)(bk * NC + c) * NST) * DIN + d;
        #pragma unroll
        for (int n = 0; n < NST; n++)
            g_chQ[basep + (size_t)n * DIN] = h[n];
        g_csd[((size_t)bk * NC + c) * DIN + d] = sdv;
    }
}

// ---------------- kernel 5: scan phase B (latency-hidden chunk chain) --------
// Phase 1: batch-load sd (64 independent LDG), precompute eP into smem.
// Phase 2: serial chain with depth-8 register prefetch of Q.
__global__ __launch_bounds__(192) void k_scanB(const float* __restrict__ Alogs) {
    __shared__ float s_eP[NC][DIN];   // 48KB; thread d owns column d (conflict-free)
    int n  = blockIdx.x;     // state index
    int bk = blockIdx.y;
    int d  = threadIdx.x;
    int kd = (bk & 3) * DIN + d;
    float a = -expf(Alogs[(size_t)kd * NST + n]);
    const float* sdp = g_csd + (size_t)bk * NC * DIN + d;
    // phase 1: independent loads + exp (own column only, no sync needed)
    #pragma unroll 8
    for (int c = 0; c < NC; c++) {
        float sd = sdp[(size_t)c * DIN];
        s_eP[c][d] = __expf(a * sd);
    }
    // phase 2: pipelined chain
    size_t qbase = ((size_t)(bk * NC) * NST + n) * DIN + d;
    const size_t cstr = (size_t)NST * DIN;
    const float* qp = g_chQ + qbase;
    float* h0p = g_h0 + qbase;
    float Qb[PF], Qn[PF];
    #pragma unroll
    for (int j = 0; j < PF; j++) Qb[j] = qp[(size_t)j * cstr];
    float h = 0.f;
    for (int c0 = 0; c0 < NC; c0 += PF) {
        if (c0 + PF < NC) {
            #pragma unroll
            for (int j = 0; j < PF; j++) Qn[j] = qp[(size_t)(c0 + PF + j) * cstr];
        }
        #pragma unroll
        for (int j = 0; j < PF; j++) {
            int c = c0 + j;
            h0p[(size_t)c * cstr] = h;
            h = fmaf(s_eP[c][d], h, Qb[j]);
        }
        #pragma unroll
        for (int j = 0; j < PF; j++) Qb[j] = Qn[j];
    }
}

// ---------------- kernel 6: scan phase C (packed Horner + ye prefetch) -------
__global__ __launch_bounds__(192, 4) void k_scanC(const float* __restrict__ Alogs,
                                                  const int*   __restrict__ scan) {
    __shared__ __align__(16) float sC[LC][20];
    __shared__ int   ssid[LC];
    int d  = threadIdx.x;
    int c  = blockIdx.x;
    int bk = blockIdx.y;
    int k = bk & 3;
    int l0 = c * LC;
    const float* xd = g_xdbl + (size_t)bk * NR * L_;
    for (int i = d; i < NST * LC; i += 192) {
        int n = i >> 6, q = i & 63;
        sC[q][n] = xd[(size_t)(RNK + NST + n) * L_ + l0 + q];
    }
    if (d < LC) ssid[d] = scan[(size_t)k * L_ + l0 + d];
    int kd = k * DIN + d;
    bool fast = true;
    #pragma unroll
    for (int n = 0; n < NST; n++) {
        float av = expf(Alogs[(size_t)kd * NST + n]);
        fast = fast && (fabsf(av - (float)(n + 1)) <= 1e-3f * (float)(n + 1));
    }
    float h0[NST]; bool any = false;
    size_t base = ((size_t)(bk * NC + c) * NST) * DIN + d;
    #pragma unroll
    for (int n = 0; n < NST; n++) {
        h0[n] = g_h0[base + (size_t)n * DIN];
        any = any || (h0[n] != 0.f);
    }
    __syncthreads();
    float* yp = g_y + (size_t)bk * L_ * DIN;
    const float2* yev = g_yev + ((size_t)bk * L_ + l0) * DIN + d;
    float sacc = 0.f;
    if (!any) {
        #pragma unroll 4
        for (int i = 0; i < LC; i++) {
            float yv = yev[(size_t)i * DIN].x;
            yp[(size_t)ssid[i] * DIN + d] = yv;
            sacc += yv;
        }
    } else if (fast) {
        u64 H0p[8];
        #pragma unroll
        for (int j = 0; j < 8; j++) H0p[j] = fpack2(h0[2*j], h0[2*j+1]);
        float2 ye[PF], yen[PF];
        #pragma unroll
        for (int j = 0; j < PF; j++) ye[j] = yev[(size_t)j * DIN];
        for (int i0 = 0; i0 < LC; i0 += PF) {
            if (i0 + PF < LC) {
                #pragma unroll
                for (int j = 0; j < PF; j++) yen[j] = yev[(size_t)(i0 + PF + j) * DIN];
            }
            #pragma unroll
            for (int j = 0; j < PF; j++) {
                int i = i0 + j;
                float yv = ye[j].x;
                float e  = ye[j].y;
                float e2f = e * e;
                u64 ee2 = fpack2(e2f, e2f);
                const ulonglong2* Cq = (const ulonglong2*)&sC[i][0];
                ulonglong2 c01 = Cq[0], c23 = Cq[1], c45 = Cq[2], c67 = Cq[3];
                u64 acc = fmul2p(c67.y, H0p[7]);
                acc = ffma2p(acc, ee2, fmul2p(c67.x, H0p[6]));
                acc = ffma2p(acc, ee2, fmul2p(c45.y, H0p[5]));
                acc = ffma2p(acc, ee2, fmul2p(c45.x, H0p[4]));
                acc = ffma2p(acc, ee2, fmul2p(c23.y, H0p[3]));
                acc = ffma2p(acc, ee2, fmul2p(c23.x, H0p[2]));
                acc = ffma2p(acc, ee2, fmul2p(c01.y, H0p[1]));
                acc = ffma2p(acc, ee2, fmul2p(c01.x, H0p[0]));
                float2 av = funpack2(acc);
                yv = fmaf(av.x, e, yv);       // odd powers: e * P(e^2)
                yv = fmaf(av.y, e2f, yv);     // even powers: e^2 * Q(e^2)
                yp[(size_t)ssid[i] * DIN + d] = yv;
                sacc += yv;
            }
            #pragma unroll
            for (int j = 0; j < PF; j++) ye[j] = yen[j];
        }
    } else {
        float a[NST];
        #pragma unroll
        for (int n = 0; n < NST; n++) a[n] = -expf(Alogs[(size_t)kd * NST + n]);
        #pragma unroll 1
        for (int i = 0; i < LC; i++) {
            float2 yv2 = yev[(size_t)i * DIN];
            float yv = yv2.x;
            float sdv = yv2.y;
            float corr = 0.f;
            #pragma unroll
            for (int n = 0; n < NST; n++)
                corr = fmaf(sC[i][n] * h0[n], __expf(a[n] * sdv), corr);
            yv += corr;
            yp[(size_t)ssid[i] * DIN + d] = yv;
            sacc += yv;
        }
    }
    g_psum[((size_t)bk * NC + c) * DIN + d] = sacc;
}

// ---------------- kernel 7: gates ----------------
__global__ __launch_bounds__(192) void k_gate(const float* __restrict__ gw,
                                              const float* __restrict__ gb) {
    int b = blockIdx.x, d = threadIdx.x;
    float pooled[K_];
    #pragma unroll
    for (int k = 0; k < K_; k++) {
        float s = 0.f;
        for (int c = 0; c < NC; c++)
            s += g_psum[((size_t)(b * K_ + k) * NC + c) * DIN + d];
        pooled[k] = s * (1.f / (float)L_);
    }
    #pragma unroll
    for (int o = 0; o < K_; o++) {
        float acc = gb[d * K_ + o];
        #pragma unroll
        for (int i = 0; i < K_; i++)
            acc = fmaf(pooled[i], gw[(size_t)(d * K_ + o) * K_ + i], acc);
        g_gate[(size_t)(b * DIN + d) * K_ + o] = 1.f / (1.f + __expf(-acc));
    }
}

// ---------------- kernel 8: gate-combine + LayerNorm + SiLU(z) + out GEMM ----
__global__ __launch_bounds__(256) void k_final(const float* __restrict__ lng,
                                               const float* __restrict__ lnb,
                                               const float* __restrict__ Wout,
                                               float* __restrict__ out) {
    __shared__ float a_s[32][193];
    __shared__ float w_s[96][33];
    int tid = threadIdx.x;
    int b  = blockIdx.y;
    int l0 = blockIdx.x * 32;
    int lt = tid >> 3, st = tid & 7;
    int l = l0 + lt;
    float s1 = 0.f, s2 = 0.f;
    #pragma unroll
    for (int q = 0; q < 24; q++) {
        int d = st + 8 * q;
        float4 gt = *(const float4*)&g_gate[(size_t)(b * DIN + d) * K_];
        float v = 0.f;
        v = fmaf(gt.x, g_y[((size_t)(b * K_ + 0) * L_ + l) * DIN + d], v);
        v = fmaf(gt.y, g_y[((size_t)(b * K_ + 1) * L_ + l) * DIN + d], v);
        v = fmaf(gt.z, g_y[((size_t)(b * K_ + 2) * L_ + l) * DIN + d], v);
        v = fmaf(gt.w, g_y[((size_t)(b * K_ + 3) * L_ + l) * DIN + d], v);
        a_s[lt][d] = v;
        s1 += v; s2 = fmaf(v, v, s2);
    }
    #pragma unroll
    for (int off = 4; off >= 1; off >>= 1) {
        s1 += __shfl_xor_sync(0xffffffffu, s1, off, 8);
        s2 += __shfl_xor_sync(0xffffffffu, s2, off, 8);
    }
    float mu   = s1 * (1.f / (float)DIN);
    float var  = s2 * (1.f / (float)DIN) - mu * mu;
    float rstd = rsqrtf(var + 1e-5f);
    {
        const float* zrow = g_z + ((size_t)b * L_ + l) * DIN;
        #pragma unroll
        for (int q = 0; q < 24; q++) {
            int d = st + 8 * q;
            float v = a_s[lt][d];
            v = (v - mu) * rstd * lng[d] + lnb[d];
            float z = zrow[d];
            v *= z / (1.f + __expf(-z));
            a_s[lt][d] = v;
        }
    }
    int cg = tid & 31, lg2 = tid >> 5;
    float acc[4][3] = {};
    for (int k0 = 0; k0 < DIN; k0 += 32) {
        __syncthreads();
        for (int i = tid; i < 96 * 32; i += 256) {
            int cc = i >> 5, dd = i & 31;
            w_s[cc][dd] = Wout[(size_t)cc * DIN + k0 + dd];
        }
        __syncthreads();
        #pragma unroll 4
        for (int dd = 0; dd < 32; dd++) {
            float av[4];
            #pragma unroll
            for (int ii = 0; ii < 4; ii++) av[ii] = a_s[lg2 * 4 + ii][k0 + dd];
            #pragma unroll
            for (int jj = 0; jj < 3; jj++) {
                float wv = w_s[cg * 3 + jj][dd];
                #pragma unroll
                for (int ii = 0; ii < 4; ii++) acc[ii][jj] = fmaf(av[ii], wv, acc[ii][jj]);
            }
        }
    }
    #pragma unroll
    for (int ii = 0; ii < 4; ii++) {
        int ll = l0 + lg2 * 4 + ii;
        #pragma unroll
        for (int jj = 0; jj < 3; jj++)
            out[((size_t)b * L_ + ll) * C_ + cg * 3 + jj] = acc[ii][jj];
    }
}

// ---------------- launcher ----------------
extern "C" void kernel_launch(void* const* d_in, const int* in_sizes, int n_in,
                              void* d_out, int out_size) {
    const float* x     = (const float*)d_in[0];
    const float* Win   = (const float*)d_in[1];
    const float* convw = (const float*)d_in[2];
    const float* convb = (const float*)d_in[3];
    const float* xpw   = (const float*)d_in[4];
    const float* dtw   = (const float*)d_in[5];
    const float* dtb   = (const float*)d_in[6];
    const float* Alogs = (const float*)d_in[7];
    const float* Dsv   = (const float*)d_in[8];
    const float* gw    = (const float*)d_in[9];
    const float* gb    = (const float*)d_in[10];
    const float* lng   = (const float*)d_in[11];
    const float* lnb   = (const float*)d_in[12];
    const float* Wout  = (const float*)d_in[13];
    const int*   scan  = (const int*)d_in[14];
    float* out = (float*)d_out;

    k_inproj<<<dim3(6, 128), 256>>>(x, Win);
    k_conv  <<<dim3(4, H_, B_), 192>>>(convw, convb);
    k_xproj <<<dim3(L_ / 64, BK_), 128>>>(xpw, scan);
    k_scanA <<<dim3(NC, BK_), 192>>>(dtw, dtb, Alogs, Dsv, scan);
    k_scanB <<<dim3(NST, BK_), 192>>>(Alogs);
    k_scanC <<<dim3(NC, BK_), 192>>>(Alogs, scan);
    k_gate  <<<B_, 192>>>(gw, gb);
    k_final <<<dim3(L_ / 32, B_), 256>>>(lng, lnb, Wout, out);
}

// round 16
// speedup vs baseline: 1.2383x; 1.0997x over previous
#include <cuda_runtime.h>
#include <math.h>

// ---------------- problem constants ----------------
#define B_  2
#define H_  64
#define W_  64
#define C_  96
#define DIN 192
#define NST 16
#define RNK 6
#define K_  4
#define L_  4096          // H_*W_
#define NC  64            // scan chunks
#define LC  64            // L_/NC
#define NR  38            // RNK + 2*NST
#define BK_ (B_*K_)
#define PF  8             // prefetch tile

typedef unsigned long long u64;

// ---------------- scratch (device globals; no runtime alloc) ----------------
static __device__ float  g_xcpre[B_*L_*DIN];
static __device__ float  g_xconv[B_*L_*DIN];
static __device__ float  g_z    [B_*L_*DIN];
static __device__ float  g_xdbl [BK_*NR*L_];          // ((bk)*38+r)*L + l
static __device__ float  g_csd  [BK_*NC*DIN];         // per-chunk sum(delta)
static __device__ float  g_chQ  [BK_*NC*NST*DIN];     // per-chunk affine offset
static __device__ float  g_h0   [BK_*NC*NST*DIN];     // chunk initial states
static __device__ float2 g_yev  [BK_*L_*DIN];         // (.x = local y, .y = exp(-cum d))
static __device__ float  g_y    [BK_*L_*DIN];         // scattered y
static __device__ float  g_psum [BK_*NC*DIN];
static __device__ float  g_gate [B_*DIN*K_];

// ---------------- packed f32x2 helpers ----------------
__device__ __forceinline__ u64 fpack2(float lo, float hi) {
    u64 d; asm("mov.b64 %0,{%1,%2};" : "=l"(d) : "f"(lo), "f"(hi)); return d;
}
__device__ __forceinline__ float2 funpack2(u64 a) {
    float2 r; asm("mov.b64 {%0,%1},%2;" : "=f"(r.x), "=f"(r.y) : "l"(a)); return r;
}
__device__ __forceinline__ u64 fmul2p(u64 a, u64 b) {
    u64 d; asm("mul.rn.f32x2 %0,%1,%2;" : "=l"(d) : "l"(a), "l"(b)); return d;
}
__device__ __forceinline__ u64 ffma2p(u64 a, u64 b, u64 c) {
    u64 d; asm("fma.rn.f32x2 %0,%1,%2,%3;" : "=l"(d) : "l"(a), "l"(b), "l"(c)); return d;
}
__device__ __forceinline__ float softplus_fast(float t) {
    return (t > 15.f) ? t : __logf(1.f + __expf(t));
}

// ---------------- kernel 1: in_proj GEMM  (8192x384x96), packed f32x2 -------
__global__ __launch_bounds__(256) void k_inproj(const float* __restrict__ x,
                                                const float* __restrict__ Win) {
    __shared__ __align__(16) float As[32][68];
    __shared__ __align__(16) float Bs[32][68];
    int tid = threadIdx.x;
    int m0 = blockIdx.y * 64;
    int n0 = blockIdx.x * 64;
    int tm = tid & 15, tn = tid >> 4;
    u64 acc2[2][4] = {};     // [i-pair][j]
    for (int k0 = 0; k0 < 96; k0 += 32) {
        #pragma unroll
        for (int q = 0; q < 2; q++) {
            int f = tid * 2 + q;
            int m = f >> 3, kq = f & 7;
            float4 v = *(const float4*)&x[(size_t)(m0 + m) * 96 + k0 + kq * 4];
            As[kq*4+0][m] = v.x; As[kq*4+1][m] = v.y;
            As[kq*4+2][m] = v.z; As[kq*4+3][m] = v.w;
        }
        #pragma unroll
        for (int q = 0; q < 2; q++) {
            int f = tid * 2 + q;
            int n = f >> 3, kq = f & 7;
            float4 v = *(const float4*)&Win[(size_t)(n0 + n) * 96 + k0 + kq * 4];
            Bs[kq*4+0][n] = v.x; Bs[kq*4+1][n] = v.y;
            Bs[kq*4+2][n] = v.z; Bs[kq*4+3][n] = v.w;
        }
        __syncthreads();
        #pragma unroll
        for (int kk = 0; kk < 32; kk++) {
            ulonglong2 a2 = *(const ulonglong2*)&As[kk][tm*4];
            float4 b4 = *(const float4*)&Bs[kk][tn*4];
            u64 bb0 = fpack2(b4.x, b4.x);
            u64 bb1 = fpack2(b4.y, b4.y);
            u64 bb2 = fpack2(b4.z, b4.z);
            u64 bb3 = fpack2(b4.w, b4.w);
            acc2[0][0] = ffma2p(a2.x, bb0, acc2[0][0]);
            acc2[1][0] = ffma2p(a2.y, bb0, acc2[1][0]);
            acc2[0][1] = ffma2p(a2.x, bb1, acc2[0][1]);
            acc2[1][1] = ffma2p(a2.y, bb1, acc2[1][1]);
            acc2[0][2] = ffma2p(a2.x, bb2, acc2[0][2]);
            acc2[1][2] = ffma2p(a2.y, bb2, acc2[1][2]);
            acc2[0][3] = ffma2p(a2.x, bb3, acc2[0][3]);
            acc2[1][3] = ffma2p(a2.y, bb3, acc2[1][3]);
        }
        __syncthreads();
    }
    #pragma unroll
    for (int p = 0; p < 2; p++) {
        #pragma unroll
        for (int j = 0; j < 4; j++) {
            float2 v = funpack2(acc2[p][j]);
            int n = n0 + tn * 4 + j;
            int m = m0 + tm * 4 + 2 * p;
            if (n < DIN) {
                g_xcpre[(size_t)m * DIN + n]       = v.x;
                g_xcpre[(size_t)(m+1) * DIN + n]   = v.y;
            } else {
                g_z[(size_t)m * DIN + (n - DIN)]     = v.x;
                g_z[(size_t)(m+1) * DIN + (n - DIN)] = v.y;
            }
        }
    }
}

// ---------------- kernel 2: depthwise 3x3 conv (sliding window) -------------
__global__ __launch_bounds__(192) void k_conv(const float* __restrict__ cw,
                                              const float* __restrict__ cb) {
    int d = threadIdx.x;
    int b = blockIdx.z, y = blockIdx.y, xt = blockIdx.x;
    float w9[9];
    #pragma unroll
    for (int i = 0; i < 9; i++) w9[i] = cw[d * 9 + i];
    float bias = cb[d];
    const float* src = g_xcpre + (size_t)b * L_ * DIN;
    float*       dst = g_xconv + (size_t)b * L_ * DIN;
    bool y0ok = (y > 0), y2ok = (y < 63);
    int xx0 = xt * 16;
    // column window: c0 = x-1, c1 = x, c2 = x+1 ; rows y-1,y,y+1
    float c0[3], c1[3], c2[3];
    {
        int xm = xx0 - 1;
        if (xm >= 0) {
            c0[0] = y0ok ? src[(size_t)((y-1)*64 + xm) * DIN + d] : 0.f;
            c0[1] =        src[(size_t)( y   *64 + xm) * DIN + d];
            c0[2] = y2ok ? src[(size_t)((y+1)*64 + xm) * DIN + d] : 0.f;
        } else { c0[0] = c0[1] = c0[2] = 0.f; }
        c1[0] = y0ok ? src[(size_t)((y-1)*64 + xx0) * DIN + d] : 0.f;
        c1[1] =        src[(size_t)( y   *64 + xx0) * DIN + d];
        c1[2] = y2ok ? src[(size_t)((y+1)*64 + xx0) * DIN + d] : 0.f;
    }
    #pragma unroll 4
    for (int xi = 0; xi < 16; xi++) {
        int xx = xx0 + xi;
        int xp = xx + 1;
        if (xp < 64) {
            c2[0] = y0ok ? src[(size_t)((y-1)*64 + xp) * DIN + d] : 0.f;
            c2[1] =        src[(size_t)( y   *64 + xp) * DIN + d];
            c2[2] = y2ok ? src[(size_t)((y+1)*64 + xp) * DIN + d] : 0.f;
        } else { c2[0] = c2[1] = c2[2] = 0.f; }
        float acc = bias;
        acc = fmaf(c0[0], w9[0], acc);
        acc = fmaf(c1[0], w9[1], acc);
        acc = fmaf(c2[0], w9[2], acc);
        acc = fmaf(c0[1], w9[3], acc);
        acc = fmaf(c1[1], w9[4], acc);
        acc = fmaf(c2[1], w9[5], acc);
        acc = fmaf(c0[2], w9[6], acc);
        acc = fmaf(c1[2], w9[7], acc);
        acc = fmaf(c2[2], w9[8], acc);
        float s = 1.f / (1.f + __expf(-acc));
        dst[(size_t)(y * 64 + xx) * DIN + d] = acc * s;
        c0[0] = c1[0]; c0[1] = c1[1]; c0[2] = c1[2];
        c1[0] = c2[0]; c1[1] = c2[1]; c1[2] = c2[2];
    }
}

// ---------------- kernel 3: x_proj GEMM with gather, packed f32x2 ------------
__global__ __launch_bounds__(128) void k_xproj(const float* __restrict__ xpw,
                                               const int*   __restrict__ scan) {
    __shared__ __align__(16) float xs_s[32][68];
    __shared__ float ws  [40][33];
    __shared__ int   sid [64];
    int tid = threadIdx.x;
    int l0  = blockIdx.x * 64;
    int bk  = blockIdx.y;
    int b = bk >> 2, k = bk & 3;
    if (tid < 64) sid[tid] = scan[(size_t)k * L_ + l0 + tid];
    int lg = tid >> 3, rg = tid & 7;
    u64 acc2[5][2] = {};       // [j][l-pair]
    const float* xc = g_xconv + (size_t)b * L_ * DIN;
    for (int k0 = 0; k0 < DIN; k0 += 32) {
        __syncthreads();
        for (int i = tid; i < NR * 32; i += 128) {
            int r = i >> 5, c = i & 31;
            ws[r][c] = xpw[(size_t)(k * NR + r) * DIN + k0 + c];
        }
        if (tid < 64) ws[38 + (tid >> 5)][tid & 31] = 0.f;
        {
            int l = tid >> 1, half = (tid & 1) * 16;
            const float* p = &xc[(size_t)sid[l] * DIN + k0 + half];
            #pragma unroll
            for (int q = 0; q < 16; q += 4) {
                float4 v = *(const float4*)(p + q);
                xs_s[half+q+0][l] = v.x; xs_s[half+q+1][l] = v.y;
                xs_s[half+q+2][l] = v.z; xs_s[half+q+3][l] = v.w;
            }
        }
        __syncthreads();
        #pragma unroll
        for (int kk = 0; kk < 32; kk++) {
            ulonglong2 a2 = *(const ulonglong2*)&xs_s[kk][lg * 4];
            #pragma unroll
            for (int j = 0; j < 5; j++) {
                float wv = ws[rg + 8 * j][kk];
                u64 ww = fpack2(wv, wv);
                acc2[j][0] = ffma2p(ww, a2.x, acc2[j][0]);
                acc2[j][1] = ffma2p(ww, a2.y, acc2[j][1]);
            }
        }
    }
    float* outp = g_xdbl + (size_t)bk * NR * L_;
    #pragma unroll
    for (int j = 0; j < 5; j++) {
        int r = rg + 8 * j;
        if (r < NR) {
            float2 v0 = funpack2(acc2[j][0]);
            float2 v1 = funpack2(acc2[j][1]);
            float* o = &outp[(size_t)r * L_ + l0 + lg * 4];
            o[0] = v0.x; o[1] = v0.y; o[2] = v1.x; o[3] = v1.y;
        }
    }
}

// ---------------- kernel 4: scan phase A (packed f32x2 states) --------------
__global__ __launch_bounds__(192, 4) void k_scanA(const float* __restrict__ dtw,
                                                  const float* __restrict__ dtb,
                                                  const float* __restrict__ Alogs,
                                                  const float* __restrict__ Dsv,
                                                  const int*   __restrict__ scan) {
    __shared__ __align__(16) float sx[LC][40];
    __shared__ int   ssid[LC];
    int d  = threadIdx.x;
    int c  = blockIdx.x;
    int bk = blockIdx.y;
    int b = bk >> 2, k = bk & 3;
    int l0 = c * LC;
    const float* xd = g_xdbl + (size_t)bk * NR * L_;
    for (int i = d; i < NR * LC; i += 192) {
        int r = i >> 6, q = i & 63;
        sx[q][r < 6 ? r : r + 2] = xd[(size_t)r * L_ + l0 + q];
    }
    if (d < LC) ssid[d] = scan[(size_t)k * L_ + l0 + d];
    int kd = k * DIN + d;
    float wr[RNK];
    #pragma unroll
    for (int r = 0; r < RNK; r++) wr[r] = dtw[(size_t)kd * RNK + r];
    float tb = dtb[kd];
    float Dv = Dsv[kd];
    bool fast = true;
    #pragma unroll
    for (int n = 0; n < NST; n++) {
        float av = expf(Alogs[(size_t)kd * NST + n]);
        fast = fast && (fabsf(av - (float)(n + 1)) <= 1e-3f * (float)(n + 1));
    }
    __syncthreads();
    const float* xc = g_xconv + (size_t)b * L_ * DIN;
    if (fast) {
        u64 Hp[8];
        u64 z0 = fpack2(0.f, 0.f);
        #pragma unroll
        for (int j = 0; j < 8; j++) Hp[j] = z0;
        float ecum = 1.f;
        float sdv = 0.f;
        #pragma unroll 2
        for (int i = 0; i < LC; i++) {
            float xv = xc[(size_t)ssid[i] * DIN + d];
            float4 t0 = *(const float4*)&sx[i][0];
            float2 t1 = *(const float2*)&sx[i][4];
            float t = tb;
            t = fmaf(wr[0], t0.x, t); t = fmaf(wr[1], t0.y, t);
            t = fmaf(wr[2], t0.z, t); t = fmaf(wr[3], t0.w, t);
            t = fmaf(wr[4], t1.x, t); t = fmaf(wr[5], t1.y, t);
            float delta = softplus_fast(t);
            sdv += delta;
            float du = delta * xv;
            float e = __expf(-delta);
            ecum *= e;
            float e2f = e * e, e4f = e2f * e2f, e8f = e4f * e4f;
            u64 p0  = fpack2(e, e2f);
            u64 ee2 = fpack2(e2f, e2f);
            u64 ee4 = fpack2(e4f, e4f);
            u64 ee8 = fpack2(e8f, e8f);
            u64 p1 = fmul2p(p0, ee2);
            u64 p2 = fmul2p(p0, ee4);
            u64 p3 = fmul2p(p1, ee4);
            u64 p4 = fmul2p(p0, ee8);
            u64 p5 = fmul2p(p1, ee8);
            u64 p6 = fmul2p(p2, ee8);
            u64 p7 = fmul2p(p3, ee8);
            u64 dud = fpack2(du, du);
            const ulonglong2* Bq = (const ulonglong2*)&sx[i][8];
            const ulonglong2* Cq = (const ulonglong2*)&sx[i][24];
            ulonglong2 b01 = Bq[0], b23 = Bq[1], b45 = Bq[2], b67 = Bq[3];
            ulonglong2 c01 = Cq[0], c23 = Cq[1], c45 = Cq[2], c67 = Cq[3];
            Hp[0] = ffma2p(p0, Hp[0], fmul2p(dud, b01.x));
            Hp[1] = ffma2p(p1, Hp[1], fmul2p(dud, b01.y));
            Hp[2] = ffma2p(p2, Hp[2], fmul2p(dud, b23.x));
            Hp[3] = ffma2p(p3, Hp[3], fmul2p(dud, b23.y));
            Hp[4] = ffma2p(p4, Hp[4], fmul2p(dud, b45.x));
            Hp[5] = ffma2p(p5, Hp[5], fmul2p(dud, b45.y));
            Hp[6] = ffma2p(p6, Hp[6], fmul2p(dud, b67.x));
            Hp[7] = ffma2p(p7, Hp[7], fmul2p(dud, b67.y));
            u64 ysp = fpack2(Dv * xv, 0.f);
            ysp = ffma2p(Hp[0], c01.x, ysp);
            ysp = ffma2p(Hp[1], c01.y, ysp);
            ysp = ffma2p(Hp[2], c23.x, ysp);
            ysp = ffma2p(Hp[3], c23.y, ysp);
            ysp = ffma2p(Hp[4], c45.x, ysp);
            ysp = ffma2p(Hp[5], c45.y, ysp);
            ysp = ffma2p(Hp[6], c67.x, ysp);
            ysp = ffma2p(Hp[7], c67.y, ysp);
            float2 ys2 = funpack2(ysp);
            float ys = ys2.x + ys2.y;
            size_t gi = ((size_t)bk * L_ + l0 + i) * DIN + d;
            g_yev[gi] = make_float2(ys, ecum);
        }
        size_t basep = ((size_t)(bk * NC + c) * NST) * DIN + d;
        #pragma unroll
        for (int j = 0; j < 8; j++) {
            float2 hv = funpack2(Hp[j]);
            g_chQ[basep + (size_t)(2*j)   * DIN] = hv.x;
            g_chQ[basep + (size_t)(2*j+1) * DIN] = hv.y;
        }
        g_csd[((size_t)bk * NC + c) * DIN + d] = sdv;
    } else {
        float h[NST];
        #pragma unroll
        for (int n = 0; n < NST; n++) h[n] = 0.f;
        float a[NST];
        #pragma unroll
        for (int n = 0; n < NST; n++) a[n] = -expf(Alogs[(size_t)kd * NST + n]);
        float sdv = 0.f;
        #pragma unroll 1
        for (int i = 0; i < LC; i++) {
            float xv = xc[(size_t)ssid[i] * DIN + d];
            float4 t0 = *(const float4*)&sx[i][0];
            float2 t1 = *(const float2*)&sx[i][4];
            float t = tb;
            t = fmaf(wr[0], t0.x, t); t = fmaf(wr[1], t0.y, t);
            t = fmaf(wr[2], t0.z, t); t = fmaf(wr[3], t0.w, t);
            t = fmaf(wr[4], t1.x, t); t = fmaf(wr[5], t1.y, t);
            float delta = softplus_fast(t);
            sdv += delta;
            float du = delta * xv;
            float ys = Dv * xv;
            #pragma unroll
            for (int n = 0; n < NST; n++) {
                float dA = __expf(delta * a[n]);
                h[n] = fmaf(dA, h[n], du * sx[i][8 + n]);
                ys = fmaf(h[n], sx[i][24 + n], ys);
            }
            size_t gi = ((size_t)bk * L_ + l0 + i) * DIN + d;
            g_yev[gi] = make_float2(ys, sdv);
        }
        size_t basep = ((size_t)(bk * NC + c) * NST) * DIN + d;
        #pragma unroll
        for (int n = 0; n < NST; n++)
            g_chQ[basep + (size_t)n * DIN] = h[n];
        g_csd[((size_t)bk * NC + c) * DIN + d] = sdv;
    }
}

// ---------------- kernel 5: scan phase B (latency-hidden chunk chain) --------
__global__ __launch_bounds__(192) void k_scanB(const float* __restrict__ Alogs) {
    __shared__ float s_eP[NC][DIN];
    int n  = blockIdx.x;
    int bk = blockIdx.y;
    int d  = threadIdx.x;
    int kd = (bk & 3) * DIN + d;
    float a = -expf(Alogs[(size_t)kd * NST + n]);
    const float* sdp = g_csd + (size_t)bk * NC * DIN + d;
    #pragma unroll 8
    for (int c = 0; c < NC; c++) {
        float sd = sdp[(size_t)c * DIN];
        s_eP[c][d] = __expf(a * sd);
    }
    size_t qbase = ((size_t)(bk * NC) * NST + n) * DIN + d;
    const size_t cstr = (size_t)NST * DIN;
    const float* qp = g_chQ + qbase;
    float* h0p = g_h0 + qbase;
    float Qb[PF], Qn[PF];
    #pragma unroll
    for (int j = 0; j < PF; j++) Qb[j] = qp[(size_t)j * cstr];
    float h = 0.f;
    for (int c0 = 0; c0 < NC; c0 += PF) {
        if (c0 + PF < NC) {
            #pragma unroll
            for (int j = 0; j < PF; j++) Qn[j] = qp[(size_t)(c0 + PF + j) * cstr];
        }
        #pragma unroll
        for (int j = 0; j < PF; j++) {
            int c = c0 + j;
            h0p[(size_t)c * cstr] = h;
            h = fmaf(s_eP[c][d], h, Qb[j]);
        }
        #pragma unroll
        for (int j = 0; j < PF; j++) Qb[j] = Qn[j];
    }
}

// ---------------- kernel 6: scan phase C (packed Horner + ye prefetch) -------
__global__ __launch_bounds__(192, 4) void k_scanC(const float* __restrict__ Alogs,
                                                  const int*   __restrict__ scan) {
    __shared__ __align__(16) float sC[LC][20];
    __shared__ int   ssid[LC];
    int d  = threadIdx.x;
    int c  = blockIdx.x;
    int bk = blockIdx.y;
    int k = bk & 3;
    int l0 = c * LC;
    const float* xd = g_xdbl + (size_t)bk * NR * L_;
    for (int i = d; i < NST * LC; i += 192) {
        int n = i >> 6, q = i & 63;
        sC[q][n] = xd[(size_t)(RNK + NST + n) * L_ + l0 + q];
    }
    if (d < LC) ssid[d] = scan[(size_t)k * L_ + l0 + d];
    int kd = k * DIN + d;
    bool fast = true;
    #pragma unroll
    for (int n = 0; n < NST; n++) {
        float av = expf(Alogs[(size_t)kd * NST + n]);
        fast = fast && (fabsf(av - (float)(n + 1)) <= 1e-3f * (float)(n + 1));
    }
    float h0[NST]; bool any = false;
    size_t base = ((size_t)(bk * NC + c) * NST) * DIN + d;
    #pragma unroll
    for (int n = 0; n < NST; n++) {
        h0[n] = g_h0[base + (size_t)n * DIN];
        any = any || (h0[n] != 0.f);
    }
    __syncthreads();
    float* yp = g_y + (size_t)bk * L_ * DIN;
    const float2* yev = g_yev + ((size_t)bk * L_ + l0) * DIN + d;
    float sacc = 0.f;
    if (!any) {
        #pragma unroll 4
        for (int i = 0; i < LC; i++) {
            float yv = yev[(size_t)i * DIN].x;
            yp[(size_t)ssid[i] * DIN + d] = yv;
            sacc += yv;
        }
    } else if (fast) {
        u64 H0p[8];
        #pragma unroll
        for (int j = 0; j < 8; j++) H0p[j] = fpack2(h0[2*j], h0[2*j+1]);
        float2 ye[PF], yen[PF];
        #pragma unroll
        for (int j = 0; j < PF; j++) ye[j] = yev[(size_t)j * DIN];
        for (int i0 = 0; i0 < LC; i0 += PF) {
            if (i0 + PF < LC) {
                #pragma unroll
                for (int j = 0; j < PF; j++) yen[j] = yev[(size_t)(i0 + PF + j) * DIN];
            }
            #pragma unroll
            for (int j = 0; j < PF; j++) {
                int i = i0 + j;
                float yv = ye[j].x;
                float e  = ye[j].y;
                float e2f = e * e;
                u64 ee2 = fpack2(e2f, e2f);
                const ulonglong2* Cq = (const ulonglong2*)&sC[i][0];
                ulonglong2 c01 = Cq[0], c23 = Cq[1], c45 = Cq[2], c67 = Cq[3];
                u64 acc = fmul2p(c67.y, H0p[7]);
                acc = ffma2p(acc, ee2, fmul2p(c67.x, H0p[6]));
                acc = ffma2p(acc, ee2, fmul2p(c45.y, H0p[5]));
                acc = ffma2p(acc, ee2, fmul2p(c45.x, H0p[4]));
                acc = ffma2p(acc, ee2, fmul2p(c23.y, H0p[3]));
                acc = ffma2p(acc, ee2, fmul2p(c23.x, H0p[2]));
                acc = ffma2p(acc, ee2, fmul2p(c01.y, H0p[1]));
                acc = ffma2p(acc, ee2, fmul2p(c01.x, H0p[0]));
                float2 av = funpack2(acc);
                yv = fmaf(av.x, e, yv);
                yv = fmaf(av.y, e2f, yv);
                yp[(size_t)ssid[i] * DIN + d] = yv;
                sacc += yv;
            }
            #pragma unroll
            for (int j = 0; j < PF; j++) ye[j] = yen[j];
        }
    } else {
        float a[NST];
        #pragma unroll
        for (int n = 0; n < NST; n++) a[n] = -expf(Alogs[(size_t)kd * NST + n]);
        #pragma unroll 1
        for (int i = 0; i < LC; i++) {
            float2 yv2 = yev[(size_t)i * DIN];
            float yv = yv2.x;
            float sdv = yv2.y;
            float corr = 0.f;
            #pragma unroll
            for (int n = 0; n < NST; n++)
                corr = fmaf(sC[i][n] * h0[n], __expf(a[n] * sdv), corr);
            yv += corr;
            yp[(size_t)ssid[i] * DIN + d] = yv;
            sacc += yv;
        }
    }
    g_psum[((size_t)bk * NC + c) * DIN + d] = sacc;
}

// ---------------- kernel 7: gates (parallel reduce, 768 threads) -------------
__global__ __launch_bounds__(768) void k_gate(const float* __restrict__ gw,
                                              const float* __restrict__ gb) {
    __shared__ float red[4][K_][DIN];
    int b = blockIdx.x;
    int tid = threadIdx.x;
    int cg = tid / DIN;          // 0..3
    int d  = tid % DIN;
    float s[K_] = {};
    #pragma unroll 4
    for (int c = cg; c < NC; c += 4) {
        #pragma unroll
        for (int k = 0; k < K_; k++)
            s[k] += g_psum[((size_t)(b * K_ + k) * NC + c) * DIN + d];
    }
    #pragma unroll
    for (int k = 0; k < K_; k++) red[cg][k][d] = s[k];
    __syncthreads();
    if (tid < DIN) {
        int dd = tid;
        float pooled[K_];
        #pragma unroll
        for (int k = 0; k < K_; k++) {
            float t = red[0][k][dd] + red[1][k][dd] + red[2][k][dd] + red[3][k][dd];
            pooled[k] = t * (1.f / (float)L_);
        }
        #pragma unroll
        for (int o = 0; o < K_; o++) {
            float acc = gb[dd * K_ + o];
            #pragma unroll
            for (int i = 0; i < K_; i++)
                acc = fmaf(pooled[i], gw[(size_t)(dd * K_ + o) * K_ + i], acc);
            g_gate[(size_t)(b * DIN + dd) * K_ + o] = 1.f / (1.f + __expf(-acc));
        }
    }
}

// ---------------- kernel 8: gate-combine + LayerNorm + SiLU(z) + out GEMM ----
__global__ __launch_bounds__(256) void k_final(const float* __restrict__ lng,
                                               const float* __restrict__ lnb,
                                               const float* __restrict__ Wout,
                                               float* __restrict__ out) {
    __shared__ float a_s[32][193];
    __shared__ float w_s[96][33];
    int tid = threadIdx.x;
    int b  = blockIdx.y;
    int l0 = blockIdx.x * 32;
    int lt = tid >> 3, st = tid & 7;
    int l = l0 + lt;
    float s1 = 0.f, s2 = 0.f;
    #pragma unroll
    for (int q = 0; q < 24; q++) {
        int d = st + 8 * q;
        float4 gt = *(const float4*)&g_gate[(size_t)(b * DIN + d) * K_];
        float v = 0.f;
        v = fmaf(gt.x, g_y[((size_t)(b * K_ + 0) * L_ + l) * DIN + d], v);
        v = fmaf(gt.y, g_y[((size_t)(b * K_ + 1) * L_ + l) * DIN + d], v);
        v = fmaf(gt.z, g_y[((size_t)(b * K_ + 2) * L_ + l) * DIN + d], v);
        v = fmaf(gt.w, g_y[((size_t)(b * K_ + 3) * L_ + l) * DIN + d], v);
        a_s[lt][d] = v;
        s1 += v; s2 = fmaf(v, v, s2);
    }
    #pragma unroll
    for (int off = 4; off >= 1; off >>= 1) {
        s1 += __shfl_xor_sync(0xffffffffu, s1, off, 8);
        s2 += __shfl_xor_sync(0xffffffffu, s2, off, 8);
    }
    float mu   = s1 * (1.f / (float)DIN);
    float var  = s2 * (1.f / (float)DIN) - mu * mu;
    float rstd = rsqrtf(var + 1e-5f);
    {
        const float* zrow = g_z + ((size_t)b * L_ + l) * DIN;
        #pragma unroll
        for (int q = 0; q < 24; q++) {
            int d = st + 8 * q;
            float v = a_s[lt][d];
            v = (v - mu) * rstd * lng[d] + lnb[d];
            float z = zrow[d];
            v *= z / (1.f + __expf(-z));
            a_s[lt][d] = v;
        }
    }
    int cg = tid & 31, lg2 = tid >> 5;
    float acc[4][3] = {};
    for (int k0 = 0; k0 < DIN; k0 += 32) {
        __syncthreads();
        for (int i = tid; i < 96 * 32; i += 256) {
            int cc = i >> 5, dd = i & 31;
            w_s[cc][dd] = Wout[(size_t)cc * DIN + k0 + dd];
        }
        __syncthreads();
        #pragma unroll 4
        for (int dd = 0; dd < 32; dd++) {
            float av[4];
            #pragma unroll
            for (int ii = 0; ii < 4; ii++) av[ii] = a_s[lg2 * 4 + ii][k0 + dd];
            #pragma unroll
            for (int jj = 0; jj < 3; jj++) {
                float wv = w_s[cg * 3 + jj][dd];
                #pragma unroll
                for (int ii = 0; ii < 4; ii++) acc[ii][jj] = fmaf(av[ii], wv, acc[ii][jj]);
            }
        }
    }
    #pragma unroll
    for (int ii = 0; ii < 4; ii++) {
        int ll = l0 + lg2 * 4 + ii;
        #pragma unroll
        for (int jj = 0; jj < 3; jj++)
            out[((size_t)b * L_ + ll) * C_ + cg * 3 + jj] = acc[ii][jj];
    }
}

// ---------------- launcher ----------------
extern "C" void kernel_launch(void* const* d_in, const int* in_sizes, int n_in,
                              void* d_out, int out_size) {
    const float* x     = (const float*)d_in[0];
    const float* Win   = (const float*)d_in[1];
    const float* convw = (const float*)d_in[2];
    const float* convb = (const float*)d_in[3];
    const float* xpw   = (const float*)d_in[4];
    const float* dtw   = (const float*)d_in[5];
    const float* dtb   = (const float*)d_in[6];
    const float* Alogs = (const float*)d_in[7];
    const float* Dsv   = (const float*)d_in[8];
    const float* gw    = (const float*)d_in[9];
    const float* gb    = (const float*)d_in[10];
    const float* lng   = (const float*)d_in[11];
    const float* lnb   = (const float*)d_in[12];
    const float* Wout  = (const float*)d_in[13];
    const int*   scan  = (const int*)d_in[14];
    float* out = (float*)d_out;

    k_inproj<<<dim3(6, 128), 256>>>(x, Win);
    k_conv  <<<dim3(4, H_, B_), 192>>>(convw, convb);
    k_xproj <<<dim3(L_ / 64, BK_), 128>>>(xpw, scan);
    k_scanA <<<dim3(NC, BK_), 192>>>(dtw, dtb, Alogs, Dsv, scan);
    k_scanB <<<dim3(NST, BK_), 192>>>(Alogs);
    k_scanC <<<dim3(NC, BK_), 192>>>(Alogs, scan);
    k_gate  <<<B_, 768>>>(gw, gb);
    k_final <<<dim3(L_ / 32, B_), 256>>>(lng, lnb, Wout, out);
}